// round 3
// baseline (speedup 1.0000x reference)
#include <cuda_runtime.h>

// RNN_13855564496941: Euler RNN, T=1024, B=4096, H=50.
// R3: packed f32x2 (FFMA2) matvec, rows packed in pairs.
//     Thread = 8 rows x 1 col (4 f32x2 accumulators). H padded 50->56.
//     CTA = 16 cols x 7 chunks = 112 threads, grid=256, 2 CTAs/SM.
//     Weight pairs are contiguous in sW^T (LDS.128 = 2 packed operands);
//     activations stored pre-duplicated (a,a) so no repacking at use.
//     Single barrier per step, double-buffered act/partials, lagged output.

namespace {
constexpr int T_STEPS = 1024;
constexpr int B_DIM   = 4096;
constexpr int H_DIM   = 50;
constexpr int H_PAD   = 56;     // 7 chunks of 8 rows
constexpr int NC      = 16;     // batch columns per CTA
constexpr int SCH     = 7;      // row chunks
constexpr int RR      = 8;      // rows per thread (4 packed pairs)
constexpr int NTHR    = NC * SCH;   // 112 threads
constexpr int GRID    = B_DIM / NC; // 256 CTAs
constexpr float DT    = 0.1f;
constexpr float ONE_MINUS_DT = 0.9f;
}

__device__ __forceinline__ float2 ffma2(float2 a, float2 b, float2 c) {
    unsigned long long A, B, C, D;
    __builtin_memcpy(&A, &a, 8);
    __builtin_memcpy(&B, &b, 8);
    __builtin_memcpy(&C, &c, 8);
    asm("fma.rn.f32x2 %0, %1, %2, %3;" : "=l"(D) : "l"(A), "l"(B), "l"(C));
    float2 d;
    __builtin_memcpy(&d, &D, 8);
    return d;
}

__device__ __forceinline__ float one_plus_tanh(float x) {
    // 1 + tanh(x) = 2 e^{2x} / (e^{2x} + 1)
    float e = __expf(2.0f * fminf(x, 30.0f));
    return __fdividef(2.0f * e, e + 1.0f);
}

__global__ __launch_bounds__(NTHR, 2) void rnn_persist(
    const float* __restrict__ inpt,   // (T, B)
    const float* __restrict__ Jin,    // (H, 1)
    const float* __restrict__ Jrec,   // (H, H)
    const float* __restrict__ Jout,   // (1, H)
    const float* __restrict__ bias,   // (H, 1)
    const float* __restrict__ h0,     // (H, B)
    float* __restrict__ out)          // (T, B)
{
    __shared__ float  sW[H_DIM][H_PAD];       // sW[j][i] = dt*Jrec[i][j]; i>=50 -> 0
    __shared__ float2 sActD[2][H_DIM][NC];    // duplicated act (a,a), double-buffered
    __shared__ float  sPart[2][SCH][NC];      // Jout partials
    __shared__ float  sVec[3][H_PAD];         // dt*Jin, dt*bias, Jout (padded 0)

    const int tid   = threadIdx.x;
    const int col   = tid & (NC - 1);
    const int chunk = tid >> 4;               // 0..6
    const int r0    = chunk * RR;
    const int gcol  = blockIdx.x * NC + col;

    // ---- one-time init ----
    for (int idx = tid; idx < H_DIM * H_PAD; idx += NTHR) {
        int j = idx / H_PAD;
        int i = idx - j * H_PAD;
        sW[j][i] = (i < H_DIM) ? DT * Jrec[i * H_DIM + j] : 0.0f;
    }
    if (tid < H_PAD) {
        bool v = tid < H_DIM;
        sVec[0][tid] = v ? DT * Jin[tid]  : 0.0f;
        sVec[1][tid] = v ? DT * bias[tid] : 0.0f;
        sVec[2][tid] = v ? Jout[tid]      : 0.0f;
    }
    __syncthreads();

    float2 hv[4], jin[4], bs[4], jo[4];
    #pragma unroll
    for (int k = 0; k < 4; k++) {
        int r = r0 + 2 * k;
        float a = (r     < H_DIM) ? h0[(r    ) * B_DIM + gcol] : 0.0f;
        float b = (r + 1 < H_DIM) ? h0[(r + 1) * B_DIM + gcol] : 0.0f;
        hv[k]  = make_float2(a, b);
        jin[k] = make_float2(sVec[0][r], sVec[0][r + 1]);
        bs[k]  = make_float2(sVec[1][r], sVec[1][r + 1]);
        jo[k]  = make_float2(sVec[2][r], sVec[2][r + 1]);
    }

    const float* xptr = inpt + gcol;
    float*       optr = out + gcol;           // lagged by one step

    float x = *xptr;                          // prefetch x_0
    int p = 0;

    for (int t = 0; t < T_STEPS; t++) {
        float xNext = 0.0f;
        if (t + 1 < T_STEPS) xNext = xptr[B_DIM];
        xptr += B_DIM;

        // activations for owned rows, stored duplicated (a,a)
        #pragma unroll
        for (int k = 0; k < 4; k++) {
            int r = r0 + 2 * k;
            if (r < H_DIM) {
                float a0 = one_plus_tanh(hv[k].x);
                sActD[p][r][col] = make_float2(a0, a0);
            }
            if (r + 1 < H_DIM) {
                float a1 = one_plus_tanh(hv[k].y);
                sActD[p][r + 1][col] = make_float2(a1, a1);
            }
        }

        __syncthreads();   // the ONLY barrier per step

        // pipelined output of step t-1 (partials complete & fenced)
        if (chunk == 0 && t > 0) {
            float o = sPart[p ^ 1][0][col];
            #pragma unroll
            for (int q = 1; q < SCH; q++) o += sPart[p ^ 1][q][col];
            *optr = o;
            optr += B_DIM;
        }

        const float2 xx = make_float2(x, x);
        const float2 om = make_float2(ONE_MINUS_DT, ONE_MINUS_DT);
        float2 acc[4];
        #pragma unroll
        for (int k = 0; k < 4; k++)
            acc[k] = ffma2(om, hv[k], ffma2(jin[k], xx, bs[k]));

        #pragma unroll
        for (int j = 0; j < H_DIM; j++) {
            float2 a = sActD[p][j][col];      // LDS.64, broadcast across chunks
            float4 wA = *reinterpret_cast<const float4*>(&sW[j][r0]);      // rows r0..r0+3
            float4 wB = *reinterpret_cast<const float4*>(&sW[j][r0 + 4]);  // rows r0+4..r0+7
            acc[0] = ffma2(make_float2(wA.x, wA.y), a, acc[0]);
            acc[1] = ffma2(make_float2(wA.z, wA.w), a, acc[1]);
            acc[2] = ffma2(make_float2(wB.x, wB.y), a, acc[2]);
            acc[3] = ffma2(make_float2(wB.z, wB.w), a, acc[3]);
        }

        float2 pt2 = make_float2(0.0f, 0.0f);
        #pragma unroll
        for (int k = 0; k < 4; k++) {
            hv[k] = acc[k];
            pt2 = ffma2(jo[k], acc[k], pt2);
        }
        sPart[p][chunk][col] = pt2.x + pt2.y;

        x = xNext;
        p ^= 1;
    }

    // flush last output
    __syncthreads();
    if (chunk == 0) {
        float o = sPart[p ^ 1][0][col];
        #pragma unroll
        for (int q = 1; q < SCH; q++) o += sPart[p ^ 1][q][col];
        *optr = o;
    }
}

extern "C" void kernel_launch(void* const* d_in, const int* in_sizes, int n_in,
                              void* d_out, int out_size) {
    const float* inpt = (const float*)d_in[0];
    const float* Jin  = (const float*)d_in[1];
    const float* Jrec = (const float*)d_in[2];
    const float* Jout = (const float*)d_in[3];
    const float* bias = (const float*)d_in[4];
    const float* h0   = (const float*)d_in[5];
    float* out = (float*)d_out;

    rnn_persist<<<GRID, NTHR>>>(inpt, Jin, Jrec, Jout, bias, h0, out);
}

// round 4
// speedup vs baseline: 1.2655x; 1.2655x over previous
#include <cuda_runtime.h>

// RNN_13855564496941: Euler RNN, T=1024, B=4096, H=50.
// R4: warp-autonomous, barrier-free time loop.
//   Warp = 8 chunks x 4 col-groups = 32 lanes, covering 8 batch columns.
//   Lane = 8 rows (4 f32x2 pairs) x 2 adjacent cols. H padded 50->64.
//   Acts exchanged in SMEM (duplicated (a,a) pairs) with one __syncwarp;
//   output = Jout.h reduced across chunk-lanes via shfl.bfly, stored direct.
//   tanh via tanh.approx.f32. CTA = 2 warps (64 thr, 16 cols), grid = 256.

namespace {
constexpr int T_STEPS = 1024;
constexpr int B_DIM   = 4096;
constexpr int H_DIM   = 50;
constexpr int H_PAD   = 64;        // 8 chunks x 8 rows
constexpr int NCW     = 8;         // columns per warp
constexpr int NWARP   = 2;         // warps per CTA
constexpr int NC      = NCW * NWARP;   // 16 columns per CTA
constexpr int NTHR    = 32 * NWARP;    // 64 threads
constexpr int GRID    = B_DIM / NC;    // 256 CTAs
constexpr float DT    = 0.1f;
constexpr float OMDT  = 0.9f;
}

__device__ __forceinline__ float2 ffma2(float2 a, float2 b, float2 c) {
    unsigned long long A, B, C, D;
    __builtin_memcpy(&A, &a, 8);
    __builtin_memcpy(&B, &b, 8);
    __builtin_memcpy(&C, &c, 8);
    asm("fma.rn.f32x2 %0, %1, %2, %3;" : "=l"(D) : "l"(A), "l"(B), "l"(C));
    float2 d;
    __builtin_memcpy(&d, &D, 8);
    return d;
}

__device__ __forceinline__ float one_plus_tanh(float x) {
    float y;
    asm("tanh.approx.f32 %0, %1;" : "=f"(y) : "f"(x));
    return 1.0f + y;
}

__global__ __launch_bounds__(NTHR) void rnn_persist(
    const float* __restrict__ inpt,   // (T, B)
    const float* __restrict__ Jin,    // (H, 1)
    const float* __restrict__ Jrec,   // (H, H)
    const float* __restrict__ Jout,   // (1, H)
    const float* __restrict__ bias,   // (H, 1)
    const float* __restrict__ h0,     // (H, B)
    float* __restrict__ out)          // (T, B)
{
    __shared__ float  sW[H_DIM][H_PAD];    // sW[j][i] = dt*Jrec[i][j], i>=50 -> 0
    __shared__ float2 sActD[H_PAD][NC];    // duplicated acts (a,a); warp-private cols
    __shared__ float  sVec[3][H_PAD];      // dt*Jin, dt*bias, Jout (padded 0)

    const int tid   = threadIdx.x;
    const int lane  = tid & 31;
    const int warp  = tid >> 5;
    const int g     = lane & 3;            // col-group within warp
    const int chunk = lane >> 2;           // 0..7 -> rows chunk*8..chunk*8+7
    const int r0    = chunk * 8;
    const int cl    = warp * NCW + g * 2;  // CTA-local first col (even)
    const int gc    = blockIdx.x * NC + cl;

    // ---- one-time init ----
    for (int idx = tid; idx < H_DIM * H_PAD; idx += NTHR) {
        int j = idx >> 6;          // / H_PAD
        int i = idx & 63;
        sW[j][i] = (i < H_DIM) ? DT * Jrec[i * H_DIM + j] : 0.0f;
    }
    if (tid < H_PAD) {
        bool v = tid < H_DIM;
        sVec[0][tid] = v ? DT * Jin[tid]  : 0.0f;
        sVec[1][tid] = v ? DT * bias[tid] : 0.0f;
        sVec[2][tid] = v ? Jout[tid]      : 0.0f;
    }
    __syncthreads();

    // h[k][c]: rows (r0+2k, r0+2k+1) for local col c (0,1)
    float2 h[4][2], jin[4], bs[4], jo[4];
    #pragma unroll
    for (int k = 0; k < 4; k++) {
        int r = r0 + 2 * k;
        float2 ha = (r < H_DIM)
            ? *reinterpret_cast<const float2*>(&h0[r * B_DIM + gc])
            : make_float2(0.0f, 0.0f);
        float2 hb = (r + 1 < H_DIM)
            ? *reinterpret_cast<const float2*>(&h0[(r + 1) * B_DIM + gc])
            : make_float2(0.0f, 0.0f);
        h[k][0] = make_float2(ha.x, hb.x);   // col c0: rows r, r+1
        h[k][1] = make_float2(ha.y, hb.y);   // col c1
        jin[k] = make_float2(sVec[0][r], sVec[0][r + 1]);
        bs[k]  = make_float2(sVec[1][r], sVec[1][r + 1]);
        jo[k]  = make_float2(sVec[2][r], sVec[2][r + 1]);
    }

    const float* xptr = inpt + gc;
    float*       optr = out + gc;

    float2 x = *reinterpret_cast<const float2*>(xptr);   // x for both cols, step 0

    for (int t = 0; t < T_STEPS; t++) {
        float2 xN = make_float2(0.0f, 0.0f);
        if (t + 1 < T_STEPS)
            xN = *reinterpret_cast<const float2*>(xptr + B_DIM);
        xptr += B_DIM;

        // activations: row r gets float4 {a_c0, a_c0, a_c1, a_c1}
        #pragma unroll
        for (int k = 0; k < 4; k++) {
            int r = r0 + 2 * k;
            float a00 = one_plus_tanh(h[k][0].x);   // row r,   col c0
            float a01 = one_plus_tanh(h[k][1].x);   // row r,   col c1
            float a10 = one_plus_tanh(h[k][0].y);   // row r+1, col c0
            float a11 = one_plus_tanh(h[k][1].y);   // row r+1, col c1
            *reinterpret_cast<float4*>(&sActD[r][cl])     = make_float4(a00, a00, a01, a01);
            *reinterpret_cast<float4*>(&sActD[r + 1][cl]) = make_float4(a10, a10, a11, a11);
        }

        __syncwarp();    // acts visible warp-wide; also orders next step's writes

        const float2 xx0 = make_float2(x.x, x.x);
        const float2 xx1 = make_float2(x.y, x.y);
        const float2 om  = make_float2(OMDT, OMDT);
        float2 acc[4][2];
        #pragma unroll
        for (int k = 0; k < 4; k++) {
            acc[k][0] = ffma2(om, h[k][0], ffma2(jin[k], xx0, bs[k]));
            acc[k][1] = ffma2(om, h[k][1], ffma2(jin[k], xx1, bs[k]));
        }

        #pragma unroll
        for (int j = 0; j < H_DIM; j++) {
            float4 av = *reinterpret_cast<const float4*>(&sActD[j][cl]);  // 1 wf
            float2 a0 = make_float2(av.x, av.y);     // (a_c0, a_c0)
            float2 a1 = make_float2(av.z, av.w);     // (a_c1, a_c1)
            float4 wA = *reinterpret_cast<const float4*>(&sW[j][r0]);     // rows r0..r0+3
            float4 wB = *reinterpret_cast<const float4*>(&sW[j][r0 + 4]); // rows r0+4..r0+7
            float2 w0 = make_float2(wA.x, wA.y);
            float2 w1 = make_float2(wA.z, wA.w);
            float2 w2 = make_float2(wB.x, wB.y);
            float2 w3 = make_float2(wB.z, wB.w);
            acc[0][0] = ffma2(w0, a0, acc[0][0]);
            acc[0][1] = ffma2(w0, a1, acc[0][1]);
            acc[1][0] = ffma2(w1, a0, acc[1][0]);
            acc[1][1] = ffma2(w1, a1, acc[1][1]);
            acc[2][0] = ffma2(w2, a0, acc[2][0]);
            acc[2][1] = ffma2(w2, a1, acc[2][1]);
            acc[3][0] = ffma2(w3, a0, acc[3][0]);
            acc[3][1] = ffma2(w3, a1, acc[3][1]);
        }

        // h <- acc; per-col Jout partials
        float2 p0 = make_float2(0.0f, 0.0f);
        float2 p1 = make_float2(0.0f, 0.0f);
        #pragma unroll
        for (int k = 0; k < 4; k++) {
            h[k][0] = acc[k][0];
            h[k][1] = acc[k][1];
            p0 = ffma2(jo[k], acc[k][0], p0);
            p1 = ffma2(jo[k], acc[k][1], p1);
        }
        float pc0 = p0.x + p0.y;
        float pc1 = p1.x + p1.y;

        // reduce across the 8 chunk-lanes (lane bits 2..4)
        #pragma unroll
        for (int m = 4; m < 32; m <<= 1) {
            pc0 += __shfl_xor_sync(0xFFFFFFFFu, pc0, m);
            pc1 += __shfl_xor_sync(0xFFFFFFFFu, pc1, m);
        }
        if (chunk == 0)
            *reinterpret_cast<float2*>(optr) = make_float2(pc0, pc1);
        optr += B_DIM;

        x = xN;
    }
}

extern "C" void kernel_launch(void* const* d_in, const int* in_sizes, int n_in,
                              void* d_out, int out_size) {
    const float* inpt = (const float*)d_in[0];
    const float* Jin  = (const float*)d_in[1];
    const float* Jrec = (const float*)d_in[2];
    const float* Jout = (const float*)d_in[3];
    const float* bias = (const float*)d_in[4];
    const float* h0   = (const float*)d_in[5];
    float* out = (float*)d_out;

    rnn_persist<<<GRID, NTHR>>>(inpt, Jin, Jrec, Jout, bias, h0, out);
}

// round 5
// speedup vs baseline: 1.4763x; 1.1666x over previous
#include <cuda_runtime.h>

// RNN_13855564496941: Euler RNN, T=1024, B=4096, H=50.
// R5: weights-in-registers, one-warp CTAs.
//   CTA = 1 warp = 2 batch columns. Lane = rows (2l, 2l+1) x 2 cols.
//   dt*Jrec rows held in 50 f32x2 registers per lane (j-loop fully unrolled).
//   Per j: one broadcast LDS.128 of duplicated acts + 2 FFMA2.
//   Acts double-buffered in warp-private SMEM, one __syncwarp per step.
//   Output via shfl.bfly reduce, lane 0 stores float2. 2048 CTAs, 14/SM.

namespace {
constexpr int T_STEPS = 1024;
constexpr int B_DIM   = 4096;
constexpr int H_DIM   = 50;
constexpr int NPAIR   = 25;        // 25 row pairs cover 50 rows
constexpr int R_PAD   = 64;        // act rows allocated (lanes 25..31 write junk)
constexpr int GRID    = B_DIM / 2; // 2048 one-warp CTAs
constexpr float DT    = 0.1f;
constexpr float OMDT  = 0.9f;
}

__device__ __forceinline__ float2 ffma2(float2 a, float2 b, float2 c) {
    unsigned long long A, B, C, D;
    __builtin_memcpy(&A, &a, 8);
    __builtin_memcpy(&B, &b, 8);
    __builtin_memcpy(&C, &c, 8);
    asm("fma.rn.f32x2 %0, %1, %2, %3;" : "=l"(D) : "l"(A), "l"(B), "l"(C));
    float2 d;
    __builtin_memcpy(&d, &D, 8);
    return d;
}

__device__ __forceinline__ float one_plus_tanh(float x) {
    float y;
    asm("tanh.approx.f32 %0, %1;" : "=f"(y) : "f"(x));
    return 1.0f + y;
}

__global__ __launch_bounds__(32, 14) void rnn_persist(
    const float* __restrict__ inpt,   // (T, B)
    const float* __restrict__ Jin,    // (H, 1)
    const float* __restrict__ Jrec,   // (H, H)
    const float* __restrict__ Jout,   // (1, H)
    const float* __restrict__ bias,   // (H, 1)
    const float* __restrict__ h0,     // (H, B)
    float* __restrict__ out)          // (T, B)
{
    // duplicated acts: sAct[buf][j] = {a_j_c0, a_j_c0, a_j_c1, a_j_c1}
    __shared__ float4 sAct[2][R_PAD];

    const int lane = threadIdx.x & 31;
    const int r    = 2 * lane;            // first owned row
    const bool v0  = (r     < H_DIM);
    const bool v1  = (r + 1 < H_DIM);
    const int gc   = blockIdx.x * 2;      // first of 2 batch columns

    // ---- weights for owned rows, all j, in registers (fully unrolled use) ----
    float2 w[H_DIM];
    #pragma unroll
    for (int j = 0; j < H_DIM; j++) {
        float a = v0 ? DT * Jrec[r * H_DIM + j]       : 0.0f;
        float b = v1 ? DT * Jrec[(r + 1) * H_DIM + j] : 0.0f;
        w[j] = make_float2(a, b);
    }

    const float2 jin = make_float2(v0 ? DT * Jin[r]  : 0.0f, v1 ? DT * Jin[r + 1]  : 0.0f);
    const float2 bs  = make_float2(v0 ? DT * bias[r] : 0.0f, v1 ? DT * bias[r + 1] : 0.0f);
    const float2 jo  = make_float2(v0 ? Jout[r]      : 0.0f, v1 ? Jout[r + 1]      : 0.0f);

    // state: hv[c] = (h[r][gc+c], h[r+1][gc+c])
    float2 hv[2];
    {
        float2 ra = v0 ? *reinterpret_cast<const float2*>(&h0[r * B_DIM + gc])
                       : make_float2(0.0f, 0.0f);
        float2 rb = v1 ? *reinterpret_cast<const float2*>(&h0[(r + 1) * B_DIM + gc])
                       : make_float2(0.0f, 0.0f);
        hv[0] = make_float2(ra.x, rb.x);
        hv[1] = make_float2(ra.y, rb.y);
    }

    const float* xptr = inpt + gc;
    float*       optr = out + gc;

    float2 x = *reinterpret_cast<const float2*>(xptr);   // x_0 for both cols
    int p = 0;

    for (int t = 0; t < T_STEPS; t++) {
        float2 xN = make_float2(0.0f, 0.0f);
        if (t + 1 < T_STEPS)
            xN = *reinterpret_cast<const float2*>(xptr + B_DIM);
        xptr += B_DIM;

        // acts for owned rows (duplicated pairs)
        {
            float a0c0 = one_plus_tanh(hv[0].x);
            float a0c1 = one_plus_tanh(hv[1].x);
            float a1c0 = one_plus_tanh(hv[0].y);
            float a1c1 = one_plus_tanh(hv[1].y);
            sAct[p][r]     = make_float4(a0c0, a0c0, a0c1, a0c1);
            sAct[p][r + 1] = make_float4(a1c0, a1c0, a1c1, a1c1);
        }

        __syncwarp();

        float2 acc0 = ffma2(make_float2(OMDT, OMDT), hv[0],
                            ffma2(jin, make_float2(x.x, x.x), bs));
        float2 acc1 = ffma2(make_float2(OMDT, OMDT), hv[1],
                            ffma2(jin, make_float2(x.y, x.y), bs));

        #pragma unroll
        for (int j = 0; j < H_DIM; j++) {
            float4 av = sAct[p][j];                     // broadcast, 1 wavefront
            acc0 = ffma2(w[j], make_float2(av.x, av.y), acc0);
            acc1 = ffma2(w[j], make_float2(av.z, av.w), acc1);
        }

        hv[0] = acc0;
        hv[1] = acc1;

        // Jout partials and full-warp reduce
        float2 q0 = ffma2(jo, acc0, make_float2(0.0f, 0.0f));
        float2 q1 = ffma2(jo, acc1, make_float2(0.0f, 0.0f));
        float pc0 = q0.x + q0.y;
        float pc1 = q1.x + q1.y;
        #pragma unroll
        for (int m = 1; m < 32; m <<= 1) {
            pc0 += __shfl_xor_sync(0xFFFFFFFFu, pc0, m);
            pc1 += __shfl_xor_sync(0xFFFFFFFFu, pc1, m);
        }
        if (lane == 0)
            *reinterpret_cast<float2*>(optr) = make_float2(pc0, pc1);
        optr += B_DIM;

        x = xN;
        p ^= 1;
    }
}

extern "C" void kernel_launch(void* const* d_in, const int* in_sizes, int n_in,
                              void* d_out, int out_size) {
    const float* inpt = (const float*)d_in[0];
    const float* Jin  = (const float*)d_in[1];
    const float* Jrec = (const float*)d_in[2];
    const float* Jout = (const float*)d_in[3];
    const float* bias = (const float*)d_in[4];
    const float* h0   = (const float*)d_in[5];
    float* out = (float*)d_out;

    rnn_persist<<<GRID, 32>>>(inpt, Jin, Jrec, Jout, bias, h0, out);
}